// round 4
// baseline (speedup 1.0000x reference)
#include <cuda_runtime.h>
#include <cstdint>

#define NN 64
#define TT 5
#define VV 64
#define FF 256
#define TMID 2   // T//2

typedef unsigned long long u64;

__device__ __forceinline__ u64 add_f32x2(u64 a, u64 b) {
    u64 d; asm("add.rn.f32x2 %0, %1, %2;" : "=l"(d) : "l"(a), "l"(b)); return d;
}
__device__ __forceinline__ u64 fma_f32x2(u64 a, u64 b, u64 c) {
    u64 d; asm("fma.rn.f32x2 %0, %1, %2, %3;" : "=l"(d) : "l"(a), "l"(b), "l"(c)); return d;
}
__device__ __forceinline__ u64 pack2(float v) {
    u64 d; asm("mov.b64 %0, {%1, %1};" : "=l"(d) : "f"(v)); return d;
}

#define ABS2_MASK 0x7FFFFFFF7FFFFFFFULL

// Grid = 128 blocks (64 graphs x 2 halves), 512 threads each.
// Block owns 32 complete rows i of graph n's 64x64 similarity matrix.
// Thread layout: warp w covers rows {2w, 2w+1} of the half; lane>>4 selects
// the row, (lane&15)*4 selects a float4 of j. Row sums (== reference column
// sums by exact symmetry of S) reduce within 16-lane groups.
__global__ __launch_bounds__(512, 1)
void gl_kernel(const float* __restrict__ x,
               const float* __restrict__ a,
               float* __restrict__ out) {
    extern __shared__ float sm[];
    float* xsT = sm;                        // [FF][VV] transposed slice, 64 KB
    u64*   a2s = (u64*)(sm + FF * VV);      // [FF] packed (a_f, a_f), 2 KB

    const int b    = blockIdx.x;
    const int n    = b >> 1;
    const int half = b & 1;
    const int tid  = threadIdx.x;

    const float* xm = x + ((size_t)n * TT + TMID) * (size_t)(VV * FF);

    // ---- Stage xm[n] transposed: xsT[f*VV + v] = xm[v*FF + f] ----
    const float4* x4 = (const float4*)xm;
    #pragma unroll
    for (int idx = tid; idx < VV * (FF / 4); idx += 512) {
        int v  = idx >> 6;          // FF/4 == 64
        int f4 = idx & 63;
        float4 val = x4[v * (FF / 4) + f4];
        int f = f4 * 4;
        xsT[(f + 0) * VV + v] = val.x;
        xsT[(f + 1) * VV + v] = val.y;
        xsT[(f + 2) * VV + v] = val.z;
        xsT[(f + 3) * VV + v] = val.w;
    }
    if (tid < FF) a2s[tid] = pack2(a[tid]);
    __syncthreads();

    const int warp  = tid >> 5;
    const int lane  = tid & 31;
    const int i_idx = half * 32 + (warp << 1) + (lane >> 4); // row within graph
    const int j0    = (lane & 15) << 2;                      // 4 j's per lane

    u64 acc01 = 0, acc23 = 0;  // f32x2 accumulators = {0.0f, 0.0f}

    // ---- Main accumulation over f (packed f32x2) ----
    #pragma unroll 4
    for (int f = 0; f < FF; f++) {
        const float* row = &xsT[f * VV];
        ulonglong2 xj = *(const ulonglong2*)&row[j0];  // LDS.128, conflict-free
        float xin = -row[i_idx];                       // broadcast (2 addrs/warp)
        u64 av2   = a2s[f];                            // LDS.64 broadcast
        u64 xin2  = pack2(xin);

        u64 d01 = add_f32x2(xj.x, xin2) & ABS2_MASK;   // |xj - xi| (== |xi - xj|)
        u64 d23 = add_f32x2(xj.y, xin2) & ABS2_MASK;
        acc01 = fma_f32x2(av2, d01, acc01);
        acc23 = fma_f32x2(av2, d23, acc23);
    }

    // ---- exp, 16-lane row reduce, normalize, store float4 ----
    const float LOG2E = 1.4426950408889634f;
    float s0 = exp2f(__uint_as_float((unsigned)(acc01      )) * LOG2E);
    float s1 = exp2f(__uint_as_float((unsigned)(acc01 >> 32)) * LOG2E);
    float s2 = exp2f(__uint_as_float((unsigned)(acc23      )) * LOG2E);
    float s3 = exp2f(__uint_as_float((unsigned)(acc23 >> 32)) * LOG2E);

    float r = (s0 + s1) + (s2 + s3);
    #pragma unroll
    for (int off = 8; off > 0; off >>= 1)
        r += __shfl_xor_sync(0xFFFFFFFFu, r, off);   // stays within 16-lane group
    float inv = 1.0f / r;

    float4 o;
    o.x = s0 * inv; o.y = s1 * inv; o.z = s2 * inv; o.w = s3 * inv;
    *(float4*)&out[((size_t)(n * VV + i_idx)) * VV + j0] = o;
}

extern "C" void kernel_launch(void* const* d_in, const int* in_sizes, int n_in,
                              void* d_out, int out_size) {
    const float* x = (const float*)d_in[0];   // (64,5,64,256) float32
    const float* a = (const float*)d_in[1];   // (256,1) float32
    float* out = (float*)d_out;               // (64,64,64) float32

    const int smem_bytes = FF * VV * (int)sizeof(float) + FF * (int)sizeof(u64);
    cudaFuncSetAttribute(gl_kernel, cudaFuncAttributeMaxDynamicSharedMemorySize,
                         smem_bytes);
    gl_kernel<<<NN * 2, 512, smem_bytes>>>(x, a, out);
}

// round 5
// speedup vs baseline: 1.0083x; 1.0083x over previous
#include <cuda_runtime.h>
#include <cstdint>

#define NN 64
#define TT 5
#define VV 64
#define FF 256
#define TMID 2   // T//2

typedef unsigned long long u64;

__device__ __forceinline__ u64 add_f32x2(u64 a, u64 b) {
    u64 d; asm("add.rn.f32x2 %0, %1, %2;" : "=l"(d) : "l"(a), "l"(b)); return d;
}
__device__ __forceinline__ u64 fma_f32x2(u64 a, u64 b, u64 c) {
    u64 d; asm("fma.rn.f32x2 %0, %1, %2, %3;" : "=l"(d) : "l"(a), "l"(b), "l"(c)); return d;
}
__device__ __forceinline__ u64 pack2(float v) {
    u64 d; asm("mov.b64 %0, {%1, %1};" : "=l"(d) : "f"(v)); return d;
}

#define ABS2_MASK 0x7FFFFFFF7FFFFFFFULL

// Grid = 128 blocks (64 graphs x 2 halves), 512 threads each.
// Block owns 32 complete rows i of graph n's 64x64 similarity matrix.
// Thread layout: warp w covers rows {2w, 2w+1} of the half; lane>>4 selects
// the row, (lane&15)*4 selects a float4 of j. Row sums (== reference column
// sums by exact symmetry of S) reduce within 16-lane groups.
__global__ __launch_bounds__(512, 1)
void gl_kernel(const float* __restrict__ x,
               const float* __restrict__ a,
               float* __restrict__ out) {
    extern __shared__ float sm[];
    float* xsT = sm;                        // [FF][VV] transposed slice, 64 KB
    u64*   a2s = (u64*)(sm + FF * VV);      // [FF] packed (a_f, a_f), 2 KB

    const int b    = blockIdx.x;
    const int n    = b >> 1;
    const int half = b & 1;
    const int tid  = threadIdx.x;

    const float* xm = x + ((size_t)n * TT + TMID) * (size_t)(VV * FF);

    // ---- Stage xm[n] transposed: xsT[f*VV + v] = xm[v*FF + f] ----
    const float4* x4 = (const float4*)xm;
    #pragma unroll
    for (int idx = tid; idx < VV * (FF / 4); idx += 512) {
        int v  = idx >> 6;          // FF/4 == 64
        int f4 = idx & 63;
        float4 val = x4[v * (FF / 4) + f4];
        int f = f4 * 4;
        xsT[(f + 0) * VV + v] = val.x;
        xsT[(f + 1) * VV + v] = val.y;
        xsT[(f + 2) * VV + v] = val.z;
        xsT[(f + 3) * VV + v] = val.w;
    }
    if (tid < FF) a2s[tid] = pack2(a[tid]);
    __syncthreads();

    const int warp  = tid >> 5;
    const int lane  = tid & 31;
    const int i_idx = half * 32 + (warp << 1) + (lane >> 4); // row within graph
    const int j0    = (lane & 15) << 2;                      // 4 j's per lane

    u64 acc01 = 0, acc23 = 0;  // f32x2 accumulators = {0.0f, 0.0f}

    // ---- Main accumulation over f (packed f32x2) ----
    #pragma unroll 4
    for (int f = 0; f < FF; f++) {
        const float* row = &xsT[f * VV];
        ulonglong2 xj = *(const ulonglong2*)&row[j0];  // LDS.128, conflict-free
        float xin = -row[i_idx];                       // broadcast (2 addrs/warp)
        u64 av2   = a2s[f];                            // LDS.64 broadcast
        u64 xin2  = pack2(xin);

        u64 d01 = add_f32x2(xj.x, xin2) & ABS2_MASK;   // |xj - xi| (== |xi - xj|)
        u64 d23 = add_f32x2(xj.y, xin2) & ABS2_MASK;
        acc01 = fma_f32x2(av2, d01, acc01);
        acc23 = fma_f32x2(av2, d23, acc23);
    }

    // ---- exp, 16-lane row reduce, normalize, store float4 ----
    const float LOG2E = 1.4426950408889634f;
    float s0 = exp2f(__uint_as_float((unsigned)(acc01      )) * LOG2E);
    float s1 = exp2f(__uint_as_float((unsigned)(acc01 >> 32)) * LOG2E);
    float s2 = exp2f(__uint_as_float((unsigned)(acc23      )) * LOG2E);
    float s3 = exp2f(__uint_as_float((unsigned)(acc23 >> 32)) * LOG2E);

    float r = (s0 + s1) + (s2 + s3);
    #pragma unroll
    for (int off = 8; off > 0; off >>= 1)
        r += __shfl_xor_sync(0xFFFFFFFFu, r, off);   // stays within 16-lane group
    float inv = 1.0f / r;

    float4 o;
    o.x = s0 * inv; o.y = s1 * inv; o.z = s2 * inv; o.w = s3 * inv;
    *(float4*)&out[((size_t)(n * VV + i_idx)) * VV + j0] = o;
}

extern "C" void kernel_launch(void* const* d_in, const int* in_sizes, int n_in,
                              void* d_out, int out_size) {
    const float* x = (const float*)d_in[0];   // (64,5,64,256) float32
    const float* a = (const float*)d_in[1];   // (256,1) float32
    float* out = (float*)d_out;               // (64,64,64) float32

    const int smem_bytes = FF * VV * (int)sizeof(float) + FF * (int)sizeof(u64);
    cudaFuncSetAttribute(gl_kernel, cudaFuncAttributeMaxDynamicSharedMemorySize,
                         smem_bytes);
    gl_kernel<<<NN * 2, 512, smem_bytes>>>(x, a, out);
}

// round 6
// speedup vs baseline: 1.6193x; 1.6061x over previous
#include <cuda_runtime.h>

typedef unsigned long long u64;

#define NN 64
#define TT 5
#define VV 64
#define FF 256
#define TMID 2   // T//2
#define ABS2_MASK 0x7FFFFFFF7FFFFFFFULL

__device__ __forceinline__ u64 add2(u64 a, u64 b) {
    u64 d; asm("add.rn.f32x2 %0, %1, %2;" : "=l"(d) : "l"(a), "l"(b)); return d;
}
__device__ __forceinline__ u64 fma2(u64 a, u64 b, u64 c) {
    u64 d; asm("fma.rn.f32x2 %0, %1, %2, %3;" : "=l"(d) : "l"(a), "l"(b), "l"(c)); return d;
}
__device__ __forceinline__ u64 pack2(float v) {
    u64 d; asm("mov.b64 %0, {%1, %1};" : "=l"(d) : "f"(v)); return d;
}
__device__ __forceinline__ u64 swap2(u64 v) {
    u64 d;
    asm("{.reg .b32 lo, hi; mov.b64 {lo, hi}, %1; mov.b64 %0, {hi, lo};}"
        : "=l"(d) : "l"(v));
    return d;
}
__device__ __forceinline__ float lo2(u64 v) { return __uint_as_float((unsigned)v); }
__device__ __forceinline__ float hi2(u64 v) { return __uint_as_float((unsigned)(v >> 32)); }

// Grid = 128 (64 graphs x 2 halves), 256 threads.
// Block owns 32 complete rows i of graph n's 64x64 similarity matrix; the
// column-sum denominator equals the row sum by exact (bitwise) symmetry of S.
// Warp w covers rows i_base..i_base+3 x all 64 j (lane L owns j = 2L, 2L+1).
// Packing is diagonal: {(i0,j0),(i1,j1)} / {(i0,j1),(i1,j0)} so no operand
// splat is needed; xsN = -x turns the diff into add.rn.f32x2.
__global__ __launch_bounds__(256, 1)
void gl_kernel(const float* __restrict__ x,
               const float* __restrict__ a,
               float* __restrict__ out) {
    extern __shared__ float sm[];
    float* xsT = sm;                          // [FF][VV]  x transposed,  64 KB
    float* xsN = sm + FF * VV;                // [FF][VV] -x transposed,  64 KB
    u64*   a2s = (u64*)(sm + 2 * FF * VV);    // [FF] packed (a_f, a_f),   2 KB

    const int b    = blockIdx.x;
    const int n    = b >> 1;
    const int half = b & 1;
    const int tid  = threadIdx.x;
    const int lane = tid & 31;
    const int warp = tid >> 5;

    const float* xm = x + ((size_t)n * TT + TMID) * (size_t)(VV * FF);

    // ---- Stage: xsT[f*VV+v] = xm[v*FF+f], xsN = negated. ----
    // Mapping v = idx&63 puts 32 distinct v's in each warp -> STS banks are
    // conflict-free. LDG is strided (1024B) but total unique data is tiny.
    const float4* x4 = (const float4*)xm;
    #pragma unroll
    for (int idx = tid; idx < VV * (FF / 4); idx += 256) {
        int v  = idx & 63;
        int f4 = idx >> 6;
        float4 val = x4[v * (FF / 4) + f4];
        int f = f4 * 4;
        xsT[(f + 0) * VV + v] =  val.x;  xsN[(f + 0) * VV + v] = -val.x;
        xsT[(f + 1) * VV + v] =  val.y;  xsN[(f + 1) * VV + v] = -val.y;
        xsT[(f + 2) * VV + v] =  val.z;  xsN[(f + 2) * VV + v] = -val.z;
        xsT[(f + 3) * VV + v] =  val.w;  xsN[(f + 3) * VV + v] = -val.w;
    }
    if (tid < FF) a2s[tid] = pack2(a[tid]);
    __syncthreads();

    const int i_base = half * 32 + warp * 4;   // 16B-aligned in xsT rows
    const int j0     = lane << 1;

    const float* pT = xsT + i_base;
    const float* pN = xsN + j0;
    const u64*   pa = a2s;

    u64 acc1 = 0, acc2 = 0, acc3 = 0, acc4 = 0;

    // ---- Main accumulation: per f, 1 LDS.128 + 2 LDS.64, 8 packed fma-ops ----
    #pragma unroll 8
    for (int f = 0; f < FF; f++) {
        ulonglong2 xi = *(const ulonglong2*)pT;   // (xi0,xi1),(xi2,xi3) bcast
        u64 nj  = *(const u64*)pN;                // (-xj0,-xj1)
        u64 av  = pa[f];
        u64 njr = swap2(nj);                      // (-xj1,-xj0)

        acc1 = fma2(av, add2(xi.x, nj ) & ABS2_MASK, acc1); // (i0,j0)(i1,j1)
        acc2 = fma2(av, add2(xi.x, njr) & ABS2_MASK, acc2); // (i0,j1)(i1,j0)
        acc3 = fma2(av, add2(xi.y, nj ) & ABS2_MASK, acc3); // (i2,j0)(i3,j1)
        acc4 = fma2(av, add2(xi.y, njr) & ABS2_MASK, acc4); // (i2,j1)(i3,j0)

        pT += VV; pN += VV;
    }

    // ---- exp, per-row warp reduction (row sum == reference column sum) ----
    const float LOG2E = 1.4426950408889634f;
    float s_i0j0 = exp2f(lo2(acc1) * LOG2E);
    float s_i1j1 = exp2f(hi2(acc1) * LOG2E);
    float s_i0j1 = exp2f(lo2(acc2) * LOG2E);
    float s_i1j0 = exp2f(hi2(acc2) * LOG2E);
    float s_i2j0 = exp2f(lo2(acc3) * LOG2E);
    float s_i3j1 = exp2f(hi2(acc3) * LOG2E);
    float s_i2j1 = exp2f(lo2(acc4) * LOG2E);
    float s_i3j0 = exp2f(hi2(acc4) * LOG2E);

    float p0 = s_i0j0 + s_i0j1;
    float p1 = s_i1j0 + s_i1j1;
    float p2 = s_i2j0 + s_i2j1;
    float p3 = s_i3j0 + s_i3j1;
    #pragma unroll
    for (int off = 16; off > 0; off >>= 1) {
        p0 += __shfl_xor_sync(0xFFFFFFFFu, p0, off);
        p1 += __shfl_xor_sync(0xFFFFFFFFu, p1, off);
        p2 += __shfl_xor_sync(0xFFFFFFFFu, p2, off);
        p3 += __shfl_xor_sync(0xFFFFFFFFu, p3, off);
    }
    float inv0 = 1.0f / p0, inv1 = 1.0f / p1, inv2 = 1.0f / p2, inv3 = 1.0f / p3;

    float* ob = out + ((size_t)(n * VV + i_base)) * VV + j0;
    *(float2*)(ob + 0 * VV) = make_float2(s_i0j0 * inv0, s_i0j1 * inv0);
    *(float2*)(ob + 1 * VV) = make_float2(s_i1j0 * inv1, s_i1j1 * inv1);
    *(float2*)(ob + 2 * VV) = make_float2(s_i2j0 * inv2, s_i2j1 * inv2);
    *(float2*)(ob + 3 * VV) = make_float2(s_i3j0 * inv3, s_i3j1 * inv3);
}

extern "C" void kernel_launch(void* const* d_in, const int* in_sizes, int n_in,
                              void* d_out, int out_size) {
    const float* x = (const float*)d_in[0];   // (64,5,64,256) float32
    const float* a = (const float*)d_in[1];   // (256,1) float32
    float* out = (float*)d_out;               // (64,64,64) float32

    const int smem_bytes = 2 * FF * VV * (int)sizeof(float) + FF * (int)sizeof(u64);
    cudaFuncSetAttribute(gl_kernel, cudaFuncAttributeMaxDynamicSharedMemorySize,
                         smem_bytes);
    gl_kernel<<<NN * 2, 256, smem_bytes>>>(x, a, out);
}